// round 2
// baseline (speedup 1.0000x reference)
#include <cuda_runtime.h>

#define BB 4
#define SS 4096
#define DD 64
#define HH 4
#define HDD 16
#define BH (BB*HH)

// ---------------- device scratch (no allocations allowed) ----------------
__device__ float g_q[BB*HH*SS*HDD];      // 4 MB  (pre-scaled by 1/sqrt(HD))
__device__ float g_k[BB*HH*SS*HDD];      // 4 MB
__device__ float g_v[BB*HH*SS*HDD];      // 4 MB  (normalized in-place by 1/Z)
__device__ float g_Z[BB*HH*SS];          // 256 KB: per-column exp-sums
__device__ float g_concat[BB*SS*DD];     // 4 MB  attended, concat layout
__device__ float g_o[BB*SS*DD];          // 4 MB  pre-softmax output

__device__ __forceinline__ float dot16(float4 a0, float4 a1, float4 a2, float4 a3,
                                       float4 b0, float4 b1, float4 b2, float4 b3)
{
    return a0.x*b0.x + a0.y*b0.y + a0.z*b0.z + a0.w*b0.w
         + a1.x*b1.x + a1.y*b1.y + a1.z*b1.z + a1.w*b1.w
         + a2.x*b2.x + a2.y*b2.y + a2.z*b2.z + a2.w*b2.w
         + a3.x*b3.x + a3.y*b3.y + a3.z*b3.z + a3.w*b3.w;
}

// ---------------- K1: per-head projection (q, k, or v) ----------------
// grid = B*S/16 blocks, 256 threads. which: 0=q,1=k,2=v.
__global__ __launch_bounds__(256) void proj_kernel(
    const float* __restrict__ x, const float* __restrict__ W,
    const float* __restrict__ bias, int which, float scale)
{
    __shared__ float xs[16][64];
    __shared__ float wt[HH][HDD][68];   // transposed W[h][e][d], pad 68 = bank-safe

    int tid = threadIdx.x;
    int row0 = blockIdx.x * 16;         // global row index = b*S + s

    for (int i = tid; i < HH*DD*HDD; i += 256) {
        int h = i >> 10;
        int rem = i & 1023;
        int d = rem >> 4;
        int e = rem & 15;
        wt[h][e][d] = W[i];
    }
    for (int i = tid; i < 16*64; i += 256)
        xs[i>>6][i&63] = x[row0*64 + i];
    __syncthreads();

    float* out = (which == 0) ? g_q : (which == 1) ? g_k : g_v;

    int g = tid >> 6;          // 0..3
    int h = (tid >> 4) & 3;
    int e = tid & 15;
    float bval = bias[h*HDD + e];
    const float4* wrow = (const float4*)&wt[h][e][0];

    #pragma unroll
    for (int r = 0; r < 4; r++) {
        int sl = g + r*4;
        const float4* xrow = (const float4*)&xs[sl][0];
        float acc = 0.f;
        #pragma unroll
        for (int j = 0; j < 16; j++) {
            float4 xv = xrow[j];
            float4 wv = wrow[j];
            acc += xv.x*wv.x + xv.y*wv.y + xv.z*wv.z + xv.w*wv.w;
        }
        int bs = row0 + sl;
        int b = bs >> 12;
        int s = bs & (SS-1);
        out[((b*HH + h)*SS + s)*HDD + e] = (acc + bval) * scale;
    }
}

// ---------------- K2: column stats Z_t = sum_s exp(q_s . k_t) ----------------
// grid = (S/128, B*H), 128 threads; each thread owns one key column t.
__global__ __launch_bounds__(128) void colsum_kernel()
{
    __shared__ float4 qs[128][4];       // 128 query rows x 16 floats
    int bh = blockIdx.y;
    int t = blockIdx.x * 128 + threadIdx.x;

    const float4* kp = (const float4*)&g_k[(bh*SS + t)*HDD];
    float4 k0 = kp[0], k1 = kp[1], k2 = kp[2], k3 = kp[3];

    const float4* qbase = (const float4*)&g_q[bh*SS*HDD];
    float z = 0.f;

    for (int s0 = 0; s0 < SS; s0 += 128) {
        __syncthreads();
        #pragma unroll
        for (int j = 0; j < 4; j++) {
            int idx = threadIdx.x + j*128;          // 0..511 float4s
            qs[idx>>2][idx&3] = qbase[(s0<<2) + idx];
        }
        __syncthreads();
        #pragma unroll 4
        for (int s = 0; s < 128; s++) {
            float sc = dot16(qs[s][0], qs[s][1], qs[s][2], qs[s][3], k0, k1, k2, k3);
            z += __expf(sc);
        }
    }
    g_Z[bh*SS + t] = z;
}

// ---------------- K2b: v[t,e] /= Z_t (in place) ----------------
__global__ __launch_bounds__(256) void vnorm_kernel()
{
    int i = blockIdx.x * 256 + threadIdx.x;
    g_v[i] = g_v[i] * (1.0f / g_Z[i >> 4]);
}

// ---------------- K3: attended[s,:] = sum_t exp(q_s . k_t) * vnorm[t,:] ----------------
// grid = (S/128, B*H), 128 threads; each thread owns one query row s.
__global__ __launch_bounds__(128) void attend_kernel()
{
    __shared__ float4 ks[64][4];
    __shared__ float4 vs[64][4];
    int bh = blockIdx.y;
    int s = blockIdx.x * 128 + threadIdx.x;

    const float4* qp = (const float4*)&g_q[(bh*SS + s)*HDD];
    float4 q0 = qp[0], q1 = qp[1], q2 = qp[2], q3 = qp[3];
    float4 a0 = {0,0,0,0}, a1 = a0, a2 = a0, a3 = a0;

    const float4* kbase = (const float4*)&g_k[bh*SS*HDD];
    const float4* vbase = (const float4*)&g_v[bh*SS*HDD];

    for (int t0 = 0; t0 < SS; t0 += 64) {
        __syncthreads();
        #pragma unroll
        for (int j = 0; j < 2; j++) {
            int idx = threadIdx.x + j*128;          // 0..255 float4s
            ks[idx>>2][idx&3] = kbase[(t0<<2) + idx];
            vs[idx>>2][idx&3] = vbase[(t0<<2) + idx];
        }
        __syncthreads();
        #pragma unroll 4
        for (int tt = 0; tt < 64; tt++) {
            float sc = dot16(q0, q1, q2, q3, ks[tt][0], ks[tt][1], ks[tt][2], ks[tt][3]);
            float w = __expf(sc);
            float4 v0 = vs[tt][0], v1 = vs[tt][1], v2 = vs[tt][2], v3 = vs[tt][3];
            a0.x += w*v0.x; a0.y += w*v0.y; a0.z += w*v0.z; a0.w += w*v0.w;
            a1.x += w*v1.x; a1.y += w*v1.y; a1.z += w*v1.z; a1.w += w*v1.w;
            a2.x += w*v2.x; a2.y += w*v2.y; a2.z += w*v2.z; a2.w += w*v2.w;
            a3.x += w*v3.x; a3.y += w*v3.y; a3.z += w*v3.z; a3.w += w*v3.w;
        }
    }
    int b = bh >> 2, h = bh & 3;
    float4* op = (float4*)&g_concat[(b*SS + s)*DD + h*HDD];
    op[0] = a0; op[1] = a1; op[2] = a2; op[3] = a3;
}

// ---------------- K4a: O = concat @ Wo + bo ----------------
// grid = B*S/16 blocks, 256 threads (4 rows x 64 d per pass, 4 passes).
__global__ __launch_bounds__(256) void out_proj_kernel(
    const float* __restrict__ Wo, const float* __restrict__ bo)
{
    __shared__ float cs[16][64];
    __shared__ float wt[64][68];        // transposed Wo[d][c]
    int tid = threadIdx.x;
    int row0 = blockIdx.x * 16;

    for (int i = tid; i < 64*64; i += 256) {
        int c = i >> 6, d = i & 63;
        wt[d][c] = Wo[i];
    }
    for (int i = tid; i < 16*64; i += 256)
        cs[i>>6][i&63] = g_concat[row0*64 + i];
    __syncthreads();

    int d = tid & 63;
    int r = tid >> 6;
    float bb = bo[d];
    const float4* wrow = (const float4*)&wt[d][0];

    #pragma unroll
    for (int rr = 0; rr < 4; rr++) {
        int row = r + rr*4;
        const float4* crow = (const float4*)&cs[row][0];
        float acc = 0.f;
        #pragma unroll
        for (int j = 0; j < 16; j++) {
            float4 cv = crow[j];
            float4 wv = wrow[j];
            acc += cv.x*wv.x + cv.y*wv.y + cv.z*wv.z + cv.w*wv.w;
        }
        g_o[(row0 + row)*64 + d] = acc + bb;
    }
}

// ---------------- K4b: softmax over the sequence axis (per (b,d) column) ----------------
// grid = B*D = 256 blocks, 256 threads.
__global__ __launch_bounds__(256) void softmax_seq_kernel(float* __restrict__ out)
{
    __shared__ float red[256];
    int b = blockIdx.x >> 6;
    int d = blockIdx.x & 63;
    int tid = threadIdx.x;
    const float* base = &g_o[b*SS*DD + d];

    float m = -1e30f;
    for (int s = tid; s < SS; s += 256)
        m = fmaxf(m, base[s*DD]);
    red[tid] = m; __syncthreads();
    for (int w = 128; w > 0; w >>= 1) {
        if (tid < w) red[tid] = fmaxf(red[tid], red[tid+w]);
        __syncthreads();
    }
    m = red[0];
    __syncthreads();

    float sum = 0.f;
    for (int s = tid; s < SS; s += 256)
        sum += __expf(base[s*DD] - m);
    red[tid] = sum; __syncthreads();
    for (int w = 128; w > 0; w >>= 1) {
        if (tid < w) red[tid] += red[tid+w];
        __syncthreads();
    }
    float rinv = 1.0f / red[0];

    for (int s = tid; s < SS; s += 256)
        out[(b*SS + s)*DD + d] = __expf(base[s*DD] - m) * rinv;
}

// ---------------- launch ----------------
extern "C" void kernel_launch(void* const* d_in, const int* in_sizes, int n_in,
                              void* d_out, int out_size)
{
    const float* x  = (const float*)d_in[0];
    const float* Wq = (const float*)d_in[1];
    const float* bq = (const float*)d_in[2];
    const float* Wk = (const float*)d_in[3];
    const float* bk = (const float*)d_in[4];
    const float* Wv = (const float*)d_in[5];
    const float* bv = (const float*)d_in[6];
    const float* Wo = (const float*)d_in[7];
    const float* bo = (const float*)d_in[8];
    float* out = (float*)d_out;

    const float inv_sqrt_hd = 0.25f;   // 1/sqrt(16), folded into q

    proj_kernel<<<BB*SS/16, 256>>>(x, Wq, bq, 0, inv_sqrt_hd);
    proj_kernel<<<BB*SS/16, 256>>>(x, Wk, bk, 1, 1.0f);
    proj_kernel<<<BB*SS/16, 256>>>(x, Wv, bv, 2, 1.0f);

    colsum_kernel<<<dim3(SS/128, BH), 128>>>();
    vnorm_kernel<<<(BB*HH*SS*HDD)/256, 256>>>();
    attend_kernel<<<dim3(SS/128, BH), 128>>>();

    out_proj_kernel<<<BB*SS/16, 256>>>(Wo, bo);
    softmax_seq_kernel<<<BB*DD, 256>>>(out);
}

// round 3
// speedup vs baseline: 1.9728x; 1.9728x over previous
#include <cuda_runtime.h>

#define BB 4
#define SS 4096
#define DD 64
#define HH 4
#define HDD 16
#define BH (BB*HH)
#define NSC 8     // s-axis split for colsum partials
#define NTC 4     // t-axis split for attend partials

typedef unsigned long long ull;

// ---------------- device scratch (no allocations allowed) ----------------
__device__ float g_q[BB*HH*SS*HDD];        // 4 MB (pre-scaled by 1/sqrt(HD))
__device__ float g_k[BB*HH*SS*HDD];        // 4 MB
__device__ float g_v[BB*HH*SS*HDD];        // 4 MB (normalized in-place by 1/Z)
__device__ float g_Zpart[NSC*BH*SS];       // 2 MB partial column sums
__device__ ull   g_attp[NTC*BH*SS*8];      // 16 MB partial attended (16 floats per (tc,bh,s))
__device__ float g_concat[BB*SS*DD];       // 4 MB
__device__ float g_o[BB*SS*DD];            // 4 MB

// ---------------- packed f32x2 helpers ----------------
__device__ __forceinline__ ull ffma2(ull a, ull b, ull c) {
    ull d; asm("fma.rn.f32x2 %0, %1, %2, %3;" : "=l"(d) : "l"(a), "l"(b), "l"(c)); return d;
}
__device__ __forceinline__ float2 unpk(ull v) {
    float2 f; asm("mov.b64 {%0, %1}, %2;" : "=f"(f.x), "=f"(f.y) : "l"(v)); return f;
}
__device__ __forceinline__ ull pk(float lo, float hi) {
    ull r; asm("mov.b64 %0, {%1, %2};" : "=l"(r) : "f"(lo), "f"(hi)); return r;
}

// ---------------- K1: per-head projection (q, k, or v) ----------------
__global__ __launch_bounds__(256) void proj_kernel(
    const float* __restrict__ x, const float* __restrict__ W,
    const float* __restrict__ bias, int which, float scale)
{
    __shared__ float xs[16][64];
    __shared__ float wt[HH][HDD][68];

    int tid = threadIdx.x;
    int row0 = blockIdx.x * 16;

    for (int i = tid; i < HH*DD*HDD; i += 256) {
        int h = i >> 10;
        int rem = i & 1023;
        int d = rem >> 4;
        int e = rem & 15;
        wt[h][e][d] = W[i];
    }
    for (int i = tid; i < 16*64; i += 256)
        xs[i>>6][i&63] = x[row0*64 + i];
    __syncthreads();

    float* out = (which == 0) ? g_q : (which == 1) ? g_k : g_v;

    int g = tid >> 6;
    int h = (tid >> 4) & 3;
    int e = tid & 15;
    float bval = bias[h*HDD + e];
    const float4* wrow = (const float4*)&wt[h][e][0];

    #pragma unroll
    for (int r = 0; r < 4; r++) {
        int sl = g + r*4;
        const float4* xrow = (const float4*)&xs[sl][0];
        float acc = 0.f;
        #pragma unroll
        for (int j = 0; j < 16; j++) {
            float4 xv = xrow[j];
            float4 wv = wrow[j];
            acc += xv.x*wv.x + xv.y*wv.y + xv.z*wv.z + xv.w*wv.w;
        }
        int bs = row0 + sl;
        int b = bs >> 12;
        int s = bs & (SS-1);
        out[((b*HH + h)*SS + s)*HDD + e] = (acc + bval) * scale;
    }
}

// ---------------- K2: partial column sums Z_t over an s-chunk ----------------
// grid = (SS/512, BH, NSC), 256 threads; each thread owns TWO key columns.
__global__ __launch_bounds__(256) void colsum_kernel()
{
    __shared__ ulonglong2 qs[128][4];       // 128 query rows x 16 floats
    int bh = blockIdx.y, sc = blockIdx.z;
    int t0 = blockIdx.x * 512 + threadIdx.x;
    int t1 = t0 + 256;

    const ulonglong2* kpA = (const ulonglong2*)&g_k[(bh*SS + t0)*HDD];
    const ulonglong2* kpB = (const ulonglong2*)&g_k[(bh*SS + t1)*HDD];
    ulonglong2 a0 = kpA[0], a1 = kpA[1], a2 = kpA[2], a3 = kpA[3];
    ulonglong2 b0 = kpB[0], b1 = kpB[1], b2 = kpB[2], b3 = kpB[3];

    const ulonglong2* qbase =
        (const ulonglong2*)&g_q[(bh*SS + sc*(SS/NSC))*HDD];
    float zA = 0.f, zB = 0.f;

    #pragma unroll 1
    for (int tile = 0; tile < (SS/NSC)/128; tile++) {
        __syncthreads();
        #pragma unroll
        for (int j = 0; j < 2; j++) {
            int idx = threadIdx.x + j*256;           // 0..511 ulonglong2s
            ((ulonglong2*)qs)[idx] = qbase[tile*512 + idx];
        }
        __syncthreads();
        #pragma unroll 2
        for (int s = 0; s < 128; s++) {
            ulonglong2 q0 = qs[s][0], q1 = qs[s][1], q2 = qs[s][2], q3 = qs[s][3];
            ull pA = 0ULL, rA = 0ULL, pB = 0ULL, rB = 0ULL;
            pA = ffma2(q0.x, a0.x, pA); rA = ffma2(q0.y, a0.y, rA);
            pA = ffma2(q1.x, a1.x, pA); rA = ffma2(q1.y, a1.y, rA);
            pA = ffma2(q2.x, a2.x, pA); rA = ffma2(q2.y, a2.y, rA);
            pA = ffma2(q3.x, a3.x, pA); rA = ffma2(q3.y, a3.y, rA);
            pB = ffma2(q0.x, b0.x, pB); rB = ffma2(q0.y, b0.y, rB);
            pB = ffma2(q1.x, b1.x, pB); rB = ffma2(q1.y, b1.y, rB);
            pB = ffma2(q2.x, b2.x, pB); rB = ffma2(q2.y, b2.y, rB);
            pB = ffma2(q3.x, b3.x, pB); rB = ffma2(q3.y, b3.y, rB);
            float2 uA = unpk(pA), vA = unpk(rA);
            float2 uB = unpk(pB), vB = unpk(rB);
            zA += __expf((uA.x + uA.y) + (vA.x + vA.y));
            zB += __expf((uB.x + uB.y) + (vB.x + vB.y));
        }
    }
    g_Zpart[(sc*BH + bh)*SS + t0] = zA;
    g_Zpart[(sc*BH + bh)*SS + t1] = zB;
}

// ---------------- K2b: Z = sum of partials; v[t,:] *= 1/Z (in place) ----------------
__global__ __launch_bounds__(256) void vnorm_kernel()
{
    int i = blockIdx.x * 256 + threadIdx.x;      // bh*SS + t
    float z = 0.f;
    #pragma unroll
    for (int c = 0; c < NSC; c++)
        z += g_Zpart[c*BH*SS + i];
    float r = 1.0f / z;
    float4* vp = (float4*)&g_v[i*HDD];
    #pragma unroll
    for (int j = 0; j < 4; j++) {
        float4 v = vp[j];
        v.x *= r; v.y *= r; v.z *= r; v.w *= r;
        vp[j] = v;
    }
}

// ---------------- K3: partial attended over a t-chunk ----------------
// grid = (SS/256, BH, NTC), 256 threads; each thread owns one query row.
__global__ __launch_bounds__(256) void attend_kernel()
{
    __shared__ ulonglong2 ks[64][4];
    __shared__ ulonglong2 vs[64][4];
    int bh = blockIdx.y, tc = blockIdx.z;
    int s = blockIdx.x * 256 + threadIdx.x;

    const ulonglong2* qp = (const ulonglong2*)&g_q[(bh*SS + s)*HDD];
    ulonglong2 q0 = qp[0], q1 = qp[1], q2 = qp[2], q3 = qp[3];

    ull ac0 = 0ULL, ac1 = 0ULL, ac2 = 0ULL, ac3 = 0ULL,
        ac4 = 0ULL, ac5 = 0ULL, ac6 = 0ULL, ac7 = 0ULL;

    const ulonglong2* kbase =
        (const ulonglong2*)&g_k[(bh*SS + tc*(SS/NTC))*HDD];
    const ulonglong2* vbase =
        (const ulonglong2*)&g_v[(bh*SS + tc*(SS/NTC))*HDD];

    #pragma unroll 1
    for (int tile = 0; tile < (SS/NTC)/64; tile++) {
        __syncthreads();
        {
            int idx = threadIdx.x;                // 256 ulonglong2 per array
            ((ulonglong2*)ks)[idx] = kbase[tile*256 + idx];
            ((ulonglong2*)vs)[idx] = vbase[tile*256 + idx];
        }
        __syncthreads();
        #pragma unroll 2
        for (int tt = 0; tt < 64; tt++) {
            ulonglong2 k0 = ks[tt][0], k1 = ks[tt][1], k2 = ks[tt][2], k3 = ks[tt][3];
            ull pA = 0ULL, pB = 0ULL;
            pA = ffma2(q0.x, k0.x, pA); pB = ffma2(q0.y, k0.y, pB);
            pA = ffma2(q1.x, k1.x, pA); pB = ffma2(q1.y, k1.y, pB);
            pA = ffma2(q2.x, k2.x, pA); pB = ffma2(q2.y, k2.y, pB);
            pA = ffma2(q3.x, k3.x, pA); pB = ffma2(q3.y, k3.y, pB);
            float2 u = unpk(pA), v = unpk(pB);
            float w = __expf((u.x + u.y) + (v.x + v.y));
            ull ww = pk(w, w);
            ulonglong2 v0 = vs[tt][0], v1 = vs[tt][1], v2 = vs[tt][2], v3 = vs[tt][3];
            ac0 = ffma2(ww, v0.x, ac0); ac1 = ffma2(ww, v0.y, ac1);
            ac2 = ffma2(ww, v1.x, ac2); ac3 = ffma2(ww, v1.y, ac3);
            ac4 = ffma2(ww, v2.x, ac4); ac5 = ffma2(ww, v2.y, ac5);
            ac6 = ffma2(ww, v3.x, ac6); ac7 = ffma2(ww, v3.y, ac7);
        }
    }
    ulonglong2* op = (ulonglong2*)&g_attp[((ull)(tc*BH + bh)*SS + s)*8];
    op[0] = make_ulonglong2(ac0, ac1);
    op[1] = make_ulonglong2(ac2, ac3);
    op[2] = make_ulonglong2(ac4, ac5);
    op[3] = make_ulonglong2(ac6, ac7);
}

// ---------------- K3b: reduce partials into concat layout ----------------
__global__ __launch_bounds__(256) void attreduce_kernel()
{
    int i = blockIdx.x * 256 + threadIdx.x;   // float4 index into concat (262144 total)
    int row = i >> 4;                         // b*SS + s
    int c4 = i & 15;
    int b = row >> 12, s = row & (SS-1);
    int h = c4 >> 2, j = c4 & 3;
    int bh = b*HH + h;
    float4 acc = {0.f, 0.f, 0.f, 0.f};
    #pragma unroll
    for (int tc = 0; tc < NTC; tc++) {
        const float4* p = (const float4*)&g_attp[((ull)(tc*BH + bh)*SS + s)*8];
        float4 v = p[j];
        acc.x += v.x; acc.y += v.y; acc.z += v.z; acc.w += v.w;
    }
    ((float4*)g_concat)[i] = acc;
}

// ---------------- K4a: O = concat @ Wo + bo ----------------
__global__ __launch_bounds__(256) void out_proj_kernel(
    const float* __restrict__ Wo, const float* __restrict__ bo)
{
    __shared__ float cs[16][64];
    __shared__ float wt[64][68];
    int tid = threadIdx.x;
    int row0 = blockIdx.x * 16;

    for (int i = tid; i < 64*64; i += 256) {
        int c = i >> 6, d = i & 63;
        wt[d][c] = Wo[i];
    }
    for (int i = tid; i < 16*64; i += 256)
        cs[i>>6][i&63] = g_concat[row0*64 + i];
    __syncthreads();

    int d = tid & 63;
    int r = tid >> 6;
    float bb = bo[d];
    const float4* wrow = (const float4*)&wt[d][0];

    #pragma unroll
    for (int rr = 0; rr < 4; rr++) {
        int row = r + rr*4;
        const float4* crow = (const float4*)&cs[row][0];
        float acc = 0.f;
        #pragma unroll
        for (int j = 0; j < 16; j++) {
            float4 cv = crow[j];
            float4 wv = wrow[j];
            acc += cv.x*wv.x + cv.y*wv.y + cv.z*wv.z + cv.w*wv.w;
        }
        g_o[(row0 + row)*64 + d] = acc + bb;
    }
}

// ---------------- K4b: softmax over the sequence axis ----------------
__global__ __launch_bounds__(256) void softmax_seq_kernel(float* __restrict__ out)
{
    __shared__ float red[256];
    int b = blockIdx.x >> 6;
    int d = blockIdx.x & 63;
    int tid = threadIdx.x;
    const float* base = &g_o[b*SS*DD + d];

    float m = -1e30f;
    for (int s = tid; s < SS; s += 256)
        m = fmaxf(m, base[s*DD]);
    red[tid] = m; __syncthreads();
    for (int w = 128; w > 0; w >>= 1) {
        if (tid < w) red[tid] = fmaxf(red[tid], red[tid+w]);
        __syncthreads();
    }
    m = red[0];
    __syncthreads();

    float sum = 0.f;
    for (int s = tid; s < SS; s += 256)
        sum += __expf(base[s*DD] - m);
    red[tid] = sum; __syncthreads();
    for (int w = 128; w > 0; w >>= 1) {
        if (tid < w) red[tid] += red[tid+w];
        __syncthreads();
    }
    float rinv = 1.0f / red[0];

    for (int s = tid; s < SS; s += 256)
        out[(b*SS + s)*DD + d] = __expf(base[s*DD] - m) * rinv;
}

// ---------------- launch ----------------
extern "C" void kernel_launch(void* const* d_in, const int* in_sizes, int n_in,
                              void* d_out, int out_size)
{
    const float* x  = (const float*)d_in[0];
    const float* Wq = (const float*)d_in[1];
    const float* bq = (const float*)d_in[2];
    const float* Wk = (const float*)d_in[3];
    const float* bk = (const float*)d_in[4];
    const float* Wv = (const float*)d_in[5];
    const float* bv = (const float*)d_in[6];
    const float* Wo = (const float*)d_in[7];
    const float* bo = (const float*)d_in[8];
    float* out = (float*)d_out;

    const float inv_sqrt_hd = 0.25f;

    proj_kernel<<<BB*SS/16, 256>>>(x, Wq, bq, 0, inv_sqrt_hd);
    proj_kernel<<<BB*SS/16, 256>>>(x, Wk, bk, 1, 1.0f);
    proj_kernel<<<BB*SS/16, 256>>>(x, Wv, bv, 2, 1.0f);

    colsum_kernel<<<dim3(SS/512, BH, NSC), 256>>>();
    vnorm_kernel<<<(BH*SS)/256, 256>>>();
    attend_kernel<<<dim3(SS/256, BH, NTC), 256>>>();
    attreduce_kernel<<<(BB*SS*16)/256, 256>>>();

    out_proj_kernel<<<BB*SS/16, 256>>>(Wo, bo);
    softmax_seq_kernel<<<BB*DD, 256>>>(out);
}

// round 6
// speedup vs baseline: 6.9273x; 3.5114x over previous
#include <cuda_runtime.h>
#include <cuda_fp16.h>
#include <cstdint>

#define BB 4
#define SS 4096
#define DD 64
#define HH 4
#define HDD 16
#define BH (BB*HH)

// ---------------- device scratch ----------------
// q/k: f16, per-row 16 elements stored PERMUTED: pos(e) = 4*((e>>1)&3) + 2*(e>>3) + (e&1)
// so that each mma fragment pair {2t,2t+1,8+2t,8+2t+1} is one aligned 8-byte load.
__device__ __half g_q[BH*SS*HDD];    // 2 MB, scaled by 0.25*log2(e)
__device__ __half g_k[BH*SS*HDD];    // 2 MB
__device__ float  g_v[BH*SS*HDD];    // 4 MB, plain [bh][t][e]
__device__ __half g_vt[BH*HDD*SS];   // 2 MB, [bh*16+e][t] with the same permutation per 16-t group
__device__ float  g_Z[BH*SS];        // 256 KB
__device__ float  g_concat[BB*SS*DD];
__device__ float  g_o[BB*SS*DD];

// ---------------- helpers ----------------
__device__ __forceinline__ void mma16816(float* d,
    uint32_t a0, uint32_t a1, uint32_t a2, uint32_t a3,
    uint32_t b0, uint32_t b1)
{
    asm volatile("mma.sync.aligned.m16n8k16.row.col.f32.f16.f16.f32 "
        "{%0,%1,%2,%3}, {%4,%5,%6,%7}, {%8,%9}, {%0,%1,%2,%3};"
        : "+f"(d[0]), "+f"(d[1]), "+f"(d[2]), "+f"(d[3])
        : "r"(a0), "r"(a1), "r"(a2), "r"(a3), "r"(b0), "r"(b1));
}
// pack two f32 (lo, hi) -> f16x2, then 2^x on both halves in one MUFU op
__device__ __forceinline__ uint32_t ex2h2(float lo, float hi)
{
    uint32_t h, r;
    asm("cvt.rn.f16x2.f32 %0, %1, %2;" : "=r"(h) : "f"(hi), "f"(lo));
    asm("ex2.approx.f16x2 %0, %1;" : "=r"(r) : "r"(h));
    return r;
}
__device__ __forceinline__ float2 h2f(uint32_t u)
{
    __half2 h = *(__half2*)&u;
    return __half22float2(h);
}
__device__ __forceinline__ int permpos(int e)
{
    return 4*((e>>1)&3) + 2*(e>>3) + (e&1);
}

// ---------------- K1: per-head projection ----------------
__global__ __launch_bounds__(256) void proj_kernel(
    const float* __restrict__ x, const float* __restrict__ W,
    const float* __restrict__ bias, int which, float scale)
{
    __shared__ float xs[16][64];
    __shared__ float wt[HH][HDD][68];
    int tid = threadIdx.x;
    int row0 = blockIdx.x * 16;

    for (int i = tid; i < HH*DD*HDD; i += 256) {
        int h = i >> 10, rem = i & 1023, d = rem >> 4, e = rem & 15;
        wt[h][e][d] = W[i];
    }
    for (int i = tid; i < 16*64; i += 256)
        xs[i>>6][i&63] = x[row0*64 + i];
    __syncthreads();

    int g = tid >> 6, h = (tid >> 4) & 3, e = tid & 15;
    float bval = bias[h*HDD + e];
    const float4* wrow = (const float4*)&wt[h][e][0];
    int pp = permpos(e);

    #pragma unroll
    for (int r = 0; r < 4; r++) {
        int sl = g + r*4;
        const float4* xrow = (const float4*)&xs[sl][0];
        float acc = 0.f;
        #pragma unroll
        for (int j = 0; j < 16; j++) {
            float4 xv = xrow[j], wv = wrow[j];
            acc += xv.x*wv.x + xv.y*wv.y + xv.z*wv.z + xv.w*wv.w;
        }
        int bs = row0 + sl;
        int b = bs >> 12, s = bs & (SS-1);
        int base = ((b*HH + h)*SS + s)*HDD;
        float val = (acc + bval) * scale;
        if (which == 2)      g_v[base + e] = val;
        else if (which == 0) g_q[base + pp] = __float2half(val);
        else                 g_k[base + pp] = __float2half(val);
    }
}

// ---------------- Pass A: Z_t = sum_s 2^(q'_s . k_t) ----------------
// grid (32, BH), 256 thr. Warp w owns t rows [tb*128 + w*16, +16). A = k tile, B = q.
__global__ __launch_bounds__(256) void colsumW_kernel()
{
    int tid = threadIdx.x, w = tid >> 5, lane = tid & 31;
    int g = lane >> 2, tg = lane & 3;
    int bh = blockIdx.y;
    int trow = blockIdx.x * 128 + w * 16;

    const __half* kb = g_k + (size_t)bh*SS*HDD;
    uint2 ka = *((const uint2*)(kb + (trow + g)*HDD) + tg);
    uint2 kc = *((const uint2*)(kb + (trow + 8 + g)*HDD) + tg);
    uint32_t a0 = ka.x, a2 = ka.y, a1 = kc.x, a3 = kc.y;

    const __half* qb = g_q + (size_t)bh*SS*HDD;
    float z0 = 0.f, z1 = 0.f;

    #pragma unroll 2
    for (int s0 = 0; s0 < SS; s0 += 16) {
        uint2 q0 = *((const uint2*)(qb + (s0 + g)*HDD) + tg);      // s cols s0..s0+7
        uint2 q1 = *((const uint2*)(qb + (s0 + 8 + g)*HDD) + tg);  // s cols s0+8..15
        float d0[4] = {0,0,0,0}, d1[4] = {0,0,0,0};
        mma16816(d0, a0,a1,a2,a3, q0.x, q0.y);
        mma16816(d1, a0,a1,a2,a3, q1.x, q1.y);
        uint32_t e00 = ex2h2(d0[0], d0[1]);   // t-row g
        uint32_t e01 = ex2h2(d0[2], d0[3]);   // t-row g+8
        uint32_t e10 = ex2h2(d1[0], d1[1]);
        uint32_t e11 = ex2h2(d1[2], d1[3]);
        float2 f;
        f = h2f(e00); z0 += f.x + f.y;
        f = h2f(e10); z0 += f.x + f.y;
        f = h2f(e01); z1 += f.x + f.y;
        f = h2f(e11); z1 += f.x + f.y;
    }
    z0 += __shfl_xor_sync(0xFFFFFFFFu, z0, 1);
    z0 += __shfl_xor_sync(0xFFFFFFFFu, z0, 2);
    z1 += __shfl_xor_sync(0xFFFFFFFFu, z1, 1);
    z1 += __shfl_xor_sync(0xFFFFFFFFu, z1, 2);
    if (tg == 0) {
        g_Z[bh*SS + trow + g] = z0;
        g_Z[bh*SS + trow + 8 + g] = z1;
    }
}

// ---------------- vnorm: vt[bh][e][t] = f16(v[bh][t][e] / Z_t), t-permuted ----------------
__global__ __launch_bounds__(256) void vnorm_kernel()
{
    int i = blockIdx.x * 256 + threadIdx.x;       // bh*SS + t
    float r = 1.0f / g_Z[i];
    int bh = i >> 12, t = i & (SS-1);
    int tp = (t & ~15) + permpos(t & 15);
    const float4* vp = (const float4*)&g_v[(size_t)i*HDD];
    __half* dst = g_vt + (size_t)bh*HDD*SS + tp;
    #pragma unroll
    for (int j = 0; j < 4; j++) {
        float4 v = vp[j];
        dst[(size_t)(4*j+0)*SS] = __float2half(v.x * r);
        dst[(size_t)(4*j+1)*SS] = __float2half(v.y * r);
        dst[(size_t)(4*j+2)*SS] = __float2half(v.z * r);
        dst[(size_t)(4*j+3)*SS] = __float2half(v.w * r);
    }
}

// ---------------- Pass B: attended[s,:] = sum_t 2^(q'.k) * vnorm[t,:] ----------------
// grid (32, BH), 256 thr. Warp owns s rows [sb*128 + w*16, +16).
// MMA1: S = q @ k^T (per 16-t step); exp -> w fragment (registers); MMA2: O += w @ vt.
__global__ __launch_bounds__(256) void attendW_kernel()
{
    int tid = threadIdx.x, w = tid >> 5, lane = tid & 31;
    int g = lane >> 2, tg = lane & 3;
    int bh = blockIdx.y;
    int srow = blockIdx.x * 128 + w * 16;

    const __half* qb = g_q + (size_t)bh*SS*HDD;
    uint2 qa = *((const uint2*)(qb + (srow + g)*HDD) + tg);
    uint2 qc = *((const uint2*)(qb + (srow + 8 + g)*HDD) + tg);
    uint32_t a0 = qa.x, a2 = qa.y, a1 = qc.x, a3 = qc.y;

    const __half* kb = g_k + (size_t)bh*SS*HDD;
    const __half* vt = g_vt + (size_t)bh*HDD*SS;

    float oA[8] = {0,0,0,0,0,0,0,0};
    float oB[8] = {0,0,0,0,0,0,0,0};

    #pragma unroll 2
    for (int t0 = 0; t0 < SS; t0 += 16) {
        uint2 k0 = *((const uint2*)(kb + (t0 + g)*HDD) + tg);       // t cols t0..t0+7
        uint2 k1 = *((const uint2*)(kb + (t0 + 8 + g)*HDD) + tg);   // t cols t0+8..15
        uint2 v0 = *((const uint2*)(vt + (size_t)g*SS + t0) + tg);        // e cols 0..7
        uint2 v1 = *((const uint2*)(vt + (size_t)(8 + g)*SS + t0) + tg);  // e cols 8..15
        float d0[4] = {0,0,0,0}, d1[4] = {0,0,0,0};
        mma16816(d0, a0,a1,a2,a3, k0.x, k0.y);
        mma16816(d1, a0,a1,a2,a3, k1.x, k1.y);
        // C fragment -> A fragment identity: w regs are exactly MMA2's A operand
        uint32_t w0 = ex2h2(d0[0], d0[1]);   // (s=g,   t=2tg,2tg+1)
        uint32_t w1 = ex2h2(d0[2], d0[3]);   // (s=g+8, t=2tg,2tg+1)
        uint32_t w2 = ex2h2(d1[0], d1[1]);   // (s=g,   t=8+2tg,..)
        uint32_t w3 = ex2h2(d1[2], d1[3]);   // (s=g+8, t=8+2tg,..)
        float* o = (t0 & 16) ? oB : oA;      // 2 accumulator sets break the dep chain
        mma16816(o,     w0,w1,w2,w3, v0.x, v0.y);
        mma16816(o + 4, w0,w1,w2,w3, v1.x, v1.y);
    }

    int b = bh >> 2, h = bh & 3;
    float* dst0 = g_concat + (size_t)(b*SS + srow + g)*DD + h*HDD;
    float* dst1 = g_concat + (size_t)(b*SS + srow + 8 + g)*DD + h*HDD;
    *(float2*)(dst0 + 2*tg)     = make_float2(oA[0]+oB[0], oA[1]+oB[1]);
    *(float2*)(dst1 + 2*tg)     = make_float2(oA[2]+oB[2], oA[3]+oB[3]);
    *(float2*)(dst0 + 8 + 2*tg) = make_float2(oA[4]+oB[4], oA[5]+oB[5]);
    *(float2*)(dst1 + 8 + 2*tg) = make_float2(oA[6]+oB[6], oA[7]+oB[7]);
}

// ---------------- K4a: O = concat @ Wo + bo ----------------
__global__ __launch_bounds__(256) void out_proj_kernel(
    const float* __restrict__ Wo, const float* __restrict__ bo)
{
    __shared__ float cs[16][64];
    __shared__ float wt[64][68];
    int tid = threadIdx.x;
    int row0 = blockIdx.x * 16;

    for (int i = tid; i < 64*64; i += 256) {
        int c = i >> 6, d = i & 63;
        wt[d][c] = Wo[i];
    }
    for (int i = tid; i < 16*64; i += 256)
        cs[i>>6][i&63] = g_concat[row0*64 + i];
    __syncthreads();

    int d = tid & 63, r = tid >> 6;
    float bb = bo[d];
    const float4* wrow = (const float4*)&wt[d][0];

    #pragma unroll
    for (int rr = 0; rr < 4; rr++) {
        int row = r + rr*4;
        const float4* crow = (const float4*)&cs[row][0];
        float acc = 0.f;
        #pragma unroll
        for (int j = 0; j < 16; j++) {
            float4 cv = crow[j], wv = wrow[j];
            acc += cv.x*wv.x + cv.y*wv.y + cv.z*wv.z + cv.w*wv.w;
        }
        g_o[(row0 + row)*64 + d] = acc + bb;
    }
}

// ---------------- K4b: softmax over sequence axis ----------------
__global__ __launch_bounds__(256) void softmax_seq_kernel(float* __restrict__ out)
{
    __shared__ float red[256];
    int b = blockIdx.x >> 6, d = blockIdx.x & 63;
    int tid = threadIdx.x;
    const float* base = &g_o[b*SS*DD + d];

    float m = -1e30f;
    for (int s = tid; s < SS; s += 256) m = fmaxf(m, base[s*DD]);
    red[tid] = m; __syncthreads();
    for (int w = 128; w > 0; w >>= 1) {
        if (tid < w) red[tid] = fmaxf(red[tid], red[tid+w]);
        __syncthreads();
    }
    m = red[0]; __syncthreads();

    float sum = 0.f;
    for (int s = tid; s < SS; s += 256) sum += __expf(base[s*DD] - m);
    red[tid] = sum; __syncthreads();
    for (int w = 128; w > 0; w >>= 1) {
        if (tid < w) red[tid] += red[tid+w];
        __syncthreads();
    }
    float rinv = 1.0f / red[0];

    for (int s = tid; s < SS; s += 256)
        out[(b*SS + s)*DD + d] = __expf(base[s*DD] - m) * rinv;
}

// ---------------- launch ----------------
extern "C" void kernel_launch(void* const* d_in, const int* in_sizes, int n_in,
                              void* d_out, int out_size)
{
    const float* x  = (const float*)d_in[0];
    const float* Wq = (const float*)d_in[1];
    const float* bq = (const float*)d_in[2];
    const float* Wk = (const float*)d_in[3];
    const float* bk = (const float*)d_in[4];
    const float* Wv = (const float*)d_in[5];
    const float* bv = (const float*)d_in[6];
    const float* Wo = (const float*)d_in[7];
    const float* bo = (const float*)d_in[8];
    float* out = (float*)d_out;

    const float qscale = 0.25f * 1.4426950408889634f;  // 1/sqrt(HD) * log2(e)

    proj_kernel<<<BB*SS/16, 256>>>(x, Wq, bq, 0, qscale);
    proj_kernel<<<BB*SS/16, 256>>>(x, Wk, bk, 1, 1.0f);
    proj_kernel<<<BB*SS/16, 256>>>(x, Wv, bv, 2, 1.0f);

    colsumW_kernel<<<dim3(32, BH), 256>>>();
    vnorm_kernel<<<(BH*SS)/256, 256>>>();
    attendW_kernel<<<dim3(32, BH), 256>>>();

    out_proj_kernel<<<BB*SS/16, 256>>>(Wo, bo);
    softmax_seq_kernel<<<BB*DD, 256>>>(out);
}

// round 7
// speedup vs baseline: 7.9572x; 1.1487x over previous
#include <cuda_runtime.h>
#include <cuda_fp16.h>
#include <cstdint>

#define BB 4
#define SS 4096
#define DD 64
#define HH 4
#define HDD 16
#define BH (BB*HH)

// q/k: f16, per-row 16 elements stored PERMUTED: pos(e) = 4*((e>>1)&3) + 2*(e>>3) + (e&1)
__device__ __half g_q[BH*SS*HDD];      // 2 MB, scaled by 0.25*log2(e)
__device__ __half g_k[BH*SS*HDD];      // 2 MB
__device__ float  g_v[BH*SS*HDD];      // 4 MB
__device__ __half g_vt[BH*HDD*SS];     // 2 MB, [bh*16+e][t], t permuted per 16-group
__device__ float  g_Zpart[2*BH*SS];    // 512 KB
__device__ float  g_att[2*BB*SS*DD];   // 8 MB attend partials (concat layout)
__device__ float  g_o[BB*SS*DD];       // 4 MB, holds exp(o)
__device__ float  g_Zop[1024*64];      // 256 KB per-block column partials
__device__ float  g_Zo[BB*DD];         // final column sums

// ---------------- helpers ----------------
__device__ __forceinline__ void mma16816(float* d,
    uint32_t a0, uint32_t a1, uint32_t a2, uint32_t a3,
    uint32_t b0, uint32_t b1)
{
    asm volatile("mma.sync.aligned.m16n8k16.row.col.f32.f16.f16.f32 "
        "{%0,%1,%2,%3}, {%4,%5,%6,%7}, {%8,%9}, {%0,%1,%2,%3};"
        : "+f"(d[0]), "+f"(d[1]), "+f"(d[2]), "+f"(d[3])
        : "r"(a0), "r"(a1), "r"(a2), "r"(a3), "r"(b0), "r"(b1));
}
__device__ __forceinline__ uint32_t ex2h2(float lo, float hi)
{
    uint32_t h, r;
    asm("cvt.rn.f16x2.f32 %0, %1, %2;" : "=r"(h) : "f"(hi), "f"(lo));
    asm("ex2.approx.f16x2 %0, %1;" : "=r"(r) : "r"(h));
    return r;
}
__device__ __forceinline__ float ex2f(float x) {
    float y; asm("ex2.approx.f32 %0, %1;" : "=f"(y) : "f"(x)); return y;
}
__device__ __forceinline__ int permpos(int e)
{
    return 4*((e>>1)&3) + 2*(e>>3) + (e&1);
}

// ---------------- K1: all three projections in one grid (y = which) ----------------
__global__ __launch_bounds__(256) void proj_kernel(
    const float* __restrict__ x,
    const float* __restrict__ Wq, const float* __restrict__ bq,
    const float* __restrict__ Wk, const float* __restrict__ bk,
    const float* __restrict__ Wv, const float* __restrict__ bv,
    float qscale)
{
    __shared__ float xs[16][64];
    __shared__ float wt[HH][HDD][68];
    int which = blockIdx.y;
    const float* W    = (which == 0) ? Wq : (which == 1) ? Wk : Wv;
    const float* bias = (which == 0) ? bq : (which == 1) ? bk : bv;
    float scale = (which == 0) ? qscale : 1.0f;

    int tid = threadIdx.x;
    int row0 = blockIdx.x * 16;

    for (int i = tid; i < HH*DD*HDD; i += 256) {
        int h = i >> 10, rem = i & 1023, d = rem >> 4, e = rem & 15;
        wt[h][e][d] = W[i];
    }
    for (int i = tid; i < 16*64; i += 256)
        xs[i>>6][i&63] = x[row0*64 + i];
    __syncthreads();

    int g = tid >> 6, h = (tid >> 4) & 3, e = tid & 15;
    float bval = bias[h*HDD + e];
    const float4* wrow = (const float4*)&wt[h][e][0];
    int pp = permpos(e);

    #pragma unroll
    for (int r = 0; r < 4; r++) {
        int sl = g + r*4;
        const float4* xrow = (const float4*)&xs[sl][0];
        float acc = 0.f;
        #pragma unroll
        for (int j = 0; j < 16; j++) {
            float4 xv = xrow[j], wv = wrow[j];
            acc += xv.x*wv.x + xv.y*wv.y + xv.z*wv.z + xv.w*wv.w;
        }
        int bs = row0 + sl;
        int b = bs >> 12, s = bs & (SS-1);
        int base = ((b*HH + h)*SS + s)*HDD;
        float val = (acc + bval) * scale;
        if (which == 2)      g_v[base + e] = val;
        else if (which == 0) g_q[base + pp] = __float2half(val);
        else                 g_k[base + pp] = __float2half(val);
    }
}

// ---------------- Pass A: partial Z_t over half the s range; row-sum via MMA-ones ----------------
// grid (32, BH, 2), 256 thr. Warp owns t rows [x*128 + w*16, +16).
__global__ __launch_bounds__(256) void colsumW_kernel()
{
    int tid = threadIdx.x, w = tid >> 5, lane = tid & 31;
    int g = lane >> 2, tg = lane & 3;
    int bh = blockIdx.y, z = blockIdx.z;
    int trow = blockIdx.x * 128 + w * 16;
    const uint32_t ONE2 = 0x3C003C00u;

    const __half* kb = g_k + (size_t)bh*SS*HDD;
    uint2 ka = *((const uint2*)(kb + (trow + g)*HDD) + tg);
    uint2 kc = *((const uint2*)(kb + (trow + 8 + g)*HDD) + tg);
    uint32_t a0 = ka.x, a2 = ka.y, a1 = kc.x, a3 = kc.y;

    const __half* qb = g_q + (size_t)bh*SS*HDD + (size_t)z*(SS/2)*HDD;
    float zA[4] = {0,0,0,0}, zB[4] = {0,0,0,0};

    #pragma unroll 2
    for (int s0 = 0; s0 < SS/2; s0 += 32) {
        uint2 q0 = *((const uint2*)(qb + (s0      + g)*HDD) + tg);
        uint2 q1 = *((const uint2*)(qb + (s0 + 8  + g)*HDD) + tg);
        uint2 q2 = *((const uint2*)(qb + (s0 + 16 + g)*HDD) + tg);
        uint2 q3 = *((const uint2*)(qb + (s0 + 24 + g)*HDD) + tg);
        float d0[4]={0,0,0,0}, d1[4]={0,0,0,0}, d2[4]={0,0,0,0}, d3[4]={0,0,0,0};
        mma16816(d0, a0,a1,a2,a3, q0.x, q0.y);
        mma16816(d1, a0,a1,a2,a3, q1.x, q1.y);
        mma16816(d2, a0,a1,a2,a3, q2.x, q2.y);
        mma16816(d3, a0,a1,a2,a3, q3.x, q3.y);
        // exp -> A-fragment of a sum MMA (k-dim = s, B = ones): zA[t] += sum_s w
        uint32_t w0 = ex2h2(d0[0], d0[1]);   // (t=g,   s=2tg..)
        uint32_t w1 = ex2h2(d0[2], d0[3]);   // (t=g+8, s=2tg..)
        uint32_t w2 = ex2h2(d1[0], d1[1]);   // (t=g,   s=8+2tg..)
        uint32_t w3 = ex2h2(d1[2], d1[3]);   // (t=g+8, s=8+2tg..)
        uint32_t w4 = ex2h2(d2[0], d2[1]);
        uint32_t w5 = ex2h2(d2[2], d2[3]);
        uint32_t w6 = ex2h2(d3[0], d3[1]);
        uint32_t w7 = ex2h2(d3[2], d3[3]);
        mma16816(zA, w0,w1,w2,w3, ONE2, ONE2);
        mma16816(zB, w4,w5,w6,w7, ONE2, ONE2);
    }
    if (tg == 0) {
        g_Zpart[((size_t)z*BH + bh)*SS + trow + g]     = zA[0] + zB[0];
        g_Zpart[((size_t)z*BH + bh)*SS + trow + 8 + g] = zA[2] + zB[2];
    }
}

// ---------------- vnorm: vt[bh][e][t] = f16(v[bh][t][e] / Z_t), t-permuted ----------------
__global__ __launch_bounds__(256) void vnorm_kernel()
{
    int i = blockIdx.x * 256 + threadIdx.x;       // bh*SS + t
    float r = 1.0f / (g_Zpart[i] + g_Zpart[(size_t)BH*SS + i]);
    int bh = i >> 12, t = i & (SS-1);
    int tp = (t & ~15) + permpos(t & 15);
    const float4* vp = (const float4*)&g_v[(size_t)i*HDD];
    __half* dst = g_vt + (size_t)bh*HDD*SS + tp;
    #pragma unroll
    for (int j = 0; j < 4; j++) {
        float4 v = vp[j];
        dst[(size_t)(4*j+0)*SS] = __float2half(v.x * r);
        dst[(size_t)(4*j+1)*SS] = __float2half(v.y * r);
        dst[(size_t)(4*j+2)*SS] = __float2half(v.z * r);
        dst[(size_t)(4*j+3)*SS] = __float2half(v.w * r);
    }
}

// ---------------- Pass B: partial attended over half the t range ----------------
// grid (32, BH, 2), 256 thr. Warp owns s rows [x*128 + w*16, +16).
__global__ __launch_bounds__(256) void attendW_kernel()
{
    int tid = threadIdx.x, w = tid >> 5, lane = tid & 31;
    int g = lane >> 2, tg = lane & 3;
    int bh = blockIdx.y, z = blockIdx.z;
    int srow = blockIdx.x * 128 + w * 16;

    const __half* qb = g_q + (size_t)bh*SS*HDD;
    uint2 qa = *((const uint2*)(qb + (srow + g)*HDD) + tg);
    uint2 qc = *((const uint2*)(qb + (srow + 8 + g)*HDD) + tg);
    uint32_t a0 = qa.x, a2 = qa.y, a1 = qc.x, a3 = qc.y;

    const __half* kb = g_k + (size_t)bh*SS*HDD + (size_t)z*(SS/2)*HDD;
    const __half* vt = g_vt + (size_t)bh*HDD*SS + (size_t)z*(SS/2);

    float oA[8] = {0,0,0,0,0,0,0,0};
    float oB[8] = {0,0,0,0,0,0,0,0};

    #pragma unroll 2
    for (int t0 = 0; t0 < SS/2; t0 += 16) {
        uint2 k0 = *((const uint2*)(kb + (t0 + g)*HDD) + tg);
        uint2 k1 = *((const uint2*)(kb + (t0 + 8 + g)*HDD) + tg);
        uint2 v0 = *((const uint2*)(vt + (size_t)g*SS + t0) + tg);
        uint2 v1 = *((const uint2*)(vt + (size_t)(8 + g)*SS + t0) + tg);
        float d0[4] = {0,0,0,0}, d1[4] = {0,0,0,0};
        mma16816(d0, a0,a1,a2,a3, k0.x, k0.y);
        mma16816(d1, a0,a1,a2,a3, k1.x, k1.y);
        uint32_t w0 = ex2h2(d0[0], d0[1]);
        uint32_t w1 = ex2h2(d0[2], d0[3]);
        uint32_t w2 = ex2h2(d1[0], d1[1]);
        uint32_t w3 = ex2h2(d1[2], d1[3]);
        float* o = (t0 & 16) ? oB : oA;
        mma16816(o,     w0,w1,w2,w3, v0.x, v0.y);
        mma16816(o + 4, w0,w1,w2,w3, v1.x, v1.y);
    }

    int b = bh >> 2, h = bh & 3;
    float* att = g_att + (size_t)z*BB*SS*DD;
    float* dst0 = att + (size_t)(b*SS + srow + g)*DD + h*HDD;
    float* dst1 = att + (size_t)(b*SS + srow + 8 + g)*DD + h*HDD;
    *(float2*)(dst0 + 2*tg)     = make_float2(oA[0]+oB[0], oA[1]+oB[1]);
    *(float2*)(dst1 + 2*tg)     = make_float2(oA[2]+oB[2], oA[3]+oB[3]);
    *(float2*)(dst0 + 8 + 2*tg) = make_float2(oA[4]+oB[4], oA[5]+oB[5]);
    *(float2*)(dst1 + 8 + 2*tg) = make_float2(oA[6]+oB[6], oA[7]+oB[7]);
}

// ---------------- out_proj: o = (att0+att1) @ Wo + bo, write exp(o), column partials ----------------
__global__ __launch_bounds__(256) void out_proj_kernel(
    const float* __restrict__ Wo, const float* __restrict__ bo)
{
    __shared__ float cs[16][64];
    __shared__ float wt[64][68];
    __shared__ float red[4][64];
    int tid = threadIdx.x;
    int row0 = blockIdx.x * 16;
    const float LOG2E = 1.4426950408889634f;

    for (int i = tid; i < 64*64; i += 256) {
        int c = i >> 6, d = i & 63;
        wt[d][c] = Wo[i];
    }
    for (int i = tid; i < 16*64; i += 256)
        cs[i>>6][i&63] = g_att[row0*64 + i] + g_att[(size_t)BB*SS*DD + row0*64 + i];
    __syncthreads();

    int d = tid & 63, r = tid >> 6;
    float bb = bo[d];
    const float4* wrow = (const float4*)&wt[d][0];
    float local = 0.f;

    #pragma unroll
    for (int rr = 0; rr < 4; rr++) {
        int row = r + rr*4;
        const float4* crow = (const float4*)&cs[row][0];
        float acc = 0.f;
        #pragma unroll
        for (int j = 0; j < 16; j++) {
            float4 cv = crow[j], wv = wrow[j];
            acc += cv.x*wv.x + cv.y*wv.y + cv.z*wv.z + cv.w*wv.w;
        }
        float ev = ex2f((acc + bb) * LOG2E);    // shift-free: |o| <= ~3
        g_o[(row0 + row)*64 + d] = ev;
        local += ev;
    }
    red[r][d] = local;
    __syncthreads();
    if (r == 0)
        g_Zop[blockIdx.x*64 + d] = red[0][d] + red[1][d] + red[2][d] + red[3][d];
}

// ---------------- zsum: per-(b,d) column sums from 256 block partials ----------------
__global__ __launch_bounds__(256) void zsum_kernel()
{
    __shared__ float red[4][64];
    int b = blockIdx.x;
    int d = threadIdx.x & 63, cg = threadIdx.x >> 6;
    float s = 0.f;
    for (int c = cg; c < 256; c += 4)
        s += g_Zop[(b*256 + c)*64 + d];
    red[cg][d] = s;
    __syncthreads();
    if (cg == 0)
        g_Zo[b*64 + d] = red[0][d] + red[1][d] + red[2][d] + red[3][d];
}

// ---------------- final: out = exp(o) / Z ----------------
__global__ __launch_bounds__(256) void final_scale_kernel(float* __restrict__ out)
{
    int idx = blockIdx.x * 256 + threadIdx.x;     // float4 index, 262144 total
    int row = idx >> 4;
    int b = row >> 12;
    int d4 = idx & 15;
    float4 e = ((const float4*)g_o)[idx];
    float4 zz = ((const float4*)g_Zo)[b*16 + d4];
    float4 o;
    o.x = __fdividef(e.x, zz.x);
    o.y = __fdividef(e.y, zz.y);
    o.z = __fdividef(e.z, zz.z);
    o.w = __fdividef(e.w, zz.w);
    ((float4*)out)[idx] = o;
}

// ---------------- launch ----------------
extern "C" void kernel_launch(void* const* d_in, const int* in_sizes, int n_in,
                              void* d_out, int out_size)
{
    const float* x  = (const float*)d_in[0];
    const float* Wq = (const float*)d_in[1];
    const float* bq = (const float*)d_in[2];
    const float* Wk = (const float*)d_in[3];
    const float* bk = (const float*)d_in[4];
    const float* Wv = (const float*)d_in[5];
    const float* bv = (const float*)d_in[6];
    const float* Wo = (const float*)d_in[7];
    const float* bo = (const float*)d_in[8];
    float* out = (float*)d_out;

    const float qscale = 0.25f * 1.4426950408889634f;  // 1/sqrt(HD) * log2(e)

    proj_kernel<<<dim3(BB*SS/16, 3), 256>>>(x, Wq, bq, Wk, bk, Wv, bv, qscale);

    colsumW_kernel<<<dim3(32, BH, 2), 256>>>();
    vnorm_kernel<<<(BH*SS)/256, 256>>>();
    attendW_kernel<<<dim3(32, BH, 2), 256>>>();

    out_proj_kernel<<<BB*SS/16, 256>>>(Wo, bo);
    zsum_kernel<<<BB, 256>>>();
    final_scale_kernel<<<(BB*SS*DD/4)/256, 256>>>(out);
}

// round 8
// speedup vs baseline: 10.5611x; 1.3272x over previous
#include <cuda_runtime.h>
#include <cuda_fp16.h>
#include <cstdint>

#define BB 4
#define SS 4096
#define DD 64
#define HH 4
#define HDD 16
#define BH (BB*HH)

// q/k: f16, per-row 16 elements stored PERMUTED: pos(e) = 4*((e>>1)&3) + 2*(e>>3) + (e&1)
__device__ __half g_q[BH*SS*HDD];      // 2 MB, scaled by 0.25*log2(e)
__device__ __half g_k[BH*SS*HDD];      // 2 MB
__device__ float  g_v[BH*SS*HDD];      // 4 MB
__device__ __half g_vt[BH*HDD*SS];     // 2 MB, [bh*16+e][t], t permuted per 16-group
__device__ float  g_Zpart[2*BH*SS];    // 512 KB
__device__ float  g_att[2*BB*SS*DD];   // 8 MB attend partials (concat layout)
__device__ float  g_o[BB*SS*DD];       // 4 MB, holds exp(o)
__device__ float  g_Zop[1024*64];      // 256 KB per-block column partials
__device__ float  g_Zo[BB*DD];         // final column sums

// ---------------- helpers ----------------
__device__ __forceinline__ void mma16816(float* d,
    uint32_t a0, uint32_t a1, uint32_t a2, uint32_t a3,
    uint32_t b0, uint32_t b1)
{
    asm volatile("mma.sync.aligned.m16n8k16.row.col.f32.f16.f16.f32 "
        "{%0,%1,%2,%3}, {%4,%5,%6,%7}, {%8,%9}, {%0,%1,%2,%3};"
        : "+f"(d[0]), "+f"(d[1]), "+f"(d[2]), "+f"(d[3])
        : "r"(a0), "r"(a1), "r"(a2), "r"(a3), "r"(b0), "r"(b1));
}
__device__ __forceinline__ uint32_t ex2h2(float lo, float hi)
{
    uint32_t h, r;
    asm("cvt.rn.f16x2.f32 %0, %1, %2;" : "=r"(h) : "f"(hi), "f"(lo));
    asm("ex2.approx.f16x2 %0, %1;" : "=r"(r) : "r"(h));
    return r;
}
__device__ __forceinline__ float ex2f(float x) {
    float y; asm("ex2.approx.f32 %0, %1;" : "=f"(y) : "f"(x)); return y;
}
__device__ __forceinline__ int permpos(int e)
{
    return 4*((e>>1)&3) + 2*(e>>3) + (e&1);
}
__device__ __forceinline__ uint32_t smem_u32(const void* p) {
    uint32_t a; asm("{ .reg .u64 t; cvta.to.shared.u64 t, %1; cvt.u32.u64 %0, t; }" : "=r"(a) : "l"(p));
    return a;
}
__device__ __forceinline__ void cpa16(uint32_t s, const void* g) {
    asm volatile("cp.async.cg.shared.global [%0], [%1], 16;" :: "r"(s), "l"(g));
}
#define CP_COMMIT() asm volatile("cp.async.commit_group;")
#define CP_WAIT1()  asm volatile("cp.async.wait_group 1;")
#define CP_WAIT0()  asm volatile("cp.async.wait_group 0;")

// Fragment-order staging address for a 16-byte chunk (row r within tile, half-chunk c in 0..1):
// step = r>>4, sel = (r>>3)&1, g = r&7; chunk lands at lanes (g*4+2c, g*4+2c+1).
__device__ __forceinline__ uint32_t frag_dst(int r, int c) {
    return (uint32_t)((r>>4)*512 + ((r>>3)&1)*256 + (r&7)*32 + c*16);
}

// ---------------- K1: all three projections in one grid (y = which) ----------------
__global__ __launch_bounds__(256) void proj_kernel(
    const float* __restrict__ x,
    const float* __restrict__ Wq, const float* __restrict__ bq,
    const float* __restrict__ Wk, const float* __restrict__ bk,
    const float* __restrict__ Wv, const float* __restrict__ bv,
    float qscale)
{
    __shared__ float xs[16][64];
    __shared__ float wt[HH][HDD][68];
    int which = blockIdx.y;
    const float* W    = (which == 0) ? Wq : (which == 1) ? Wk : Wv;
    const float* bias = (which == 0) ? bq : (which == 1) ? bk : bv;
    float scale = (which == 0) ? qscale : 1.0f;

    int tid = threadIdx.x;
    int row0 = blockIdx.x * 16;

    for (int i = tid; i < HH*DD*HDD; i += 256) {
        int h = i >> 10, rem = i & 1023, d = rem >> 4, e = rem & 15;
        wt[h][e][d] = W[i];
    }
    for (int i = tid; i < 16*64; i += 256)
        xs[i>>6][i&63] = x[row0*64 + i];
    __syncthreads();

    int g = tid >> 6, h = (tid >> 4) & 3, e = tid & 15;
    float bval = bias[h*HDD + e];
    const float4* wrow = (const float4*)&wt[h][e][0];
    int pp = permpos(e);

    #pragma unroll
    for (int r = 0; r < 4; r++) {
        int sl = g + r*4;
        const float4* xrow = (const float4*)&xs[sl][0];
        float acc = 0.f;
        #pragma unroll
        for (int j = 0; j < 16; j++) {
            float4 xv = xrow[j], wv = wrow[j];
            acc += xv.x*wv.x + xv.y*wv.y + xv.z*wv.z + xv.w*wv.w;
        }
        int bs = row0 + sl;
        int b = bs >> 12, s = bs & (SS-1);
        int base = ((b*HH + h)*SS + s)*HDD;
        float val = (acc + bval) * scale;
        if (which == 2)      g_v[base + e] = val;
        else if (which == 0) g_q[base + pp] = __float2half(val);
        else                 g_k[base + pp] = __float2half(val);
    }
}

// ---------------- Pass A: partial Z_t, q tiles staged in smem ----------------
// grid (32, BH, 2), 256 thr. Warp owns t rows [x*128 + w*16, +16).
__global__ __launch_bounds__(256) void colsumW_kernel()
{
    __shared__ __align__(16) __half sq[2][2048];   // 4 KB per buffer
    int tid = threadIdx.x, w = tid >> 5, lane = tid & 31;
    int bh = blockIdx.y, z = blockIdx.z;
    int trow = blockIdx.x * 128 + w * 16;
    const uint32_t ONE2 = 0x3C003C00u;

    const __half* kb = g_k + (size_t)bh*SS*HDD;
    uint2 ka = *((const uint2*)(kb + (trow + (lane>>2))*HDD) + (lane&3));
    uint2 kc = *((const uint2*)(kb + (trow + 8 + (lane>>2))*HDD) + (lane&3));
    uint32_t a0 = ka.x, a2 = ka.y, a1 = kc.x, a3 = kc.y;

    const __half* qb = g_q + (size_t)bh*SS*HDD + (size_t)z*(SS/2)*HDD;

    // loader: chunk tid -> row r = tid>>1, half-chunk c = tid&1
    int lr = tid >> 1, lc = tid & 1;
    uint32_t qdst = frag_dst(lr, lc);
    const __half* qsrc = qb + lr*HDD + lc*8;
    uint32_t sqb = smem_u32(sq);

    float zA[4] = {0,0,0,0}, zB[4] = {0,0,0,0};

    cpa16(sqb + qdst, qsrc);
    CP_COMMIT();

    const int NT = (SS/2)/128;   // 16 tiles
    for (int tile = 0; tile < NT; tile++) {
        int buf = tile & 1;
        if (tile + 1 < NT) {
            cpa16(sqb + (buf^1)*4096 + qdst, qsrc + (size_t)(tile+1)*128*HDD);
            CP_COMMIT();
            CP_WAIT1();
        } else {
            CP_WAIT0();
        }
        __syncthreads();
        const char* qp = (const char*)sq + buf*4096 + lane*8;
        #pragma unroll
        for (int st = 0; st < 8; st++) {
            uint2 q0 = *(const uint2*)(qp + st*512);
            uint2 q1 = *(const uint2*)(qp + st*512 + 256);
            float d0[4]={0,0,0,0}, d1[4]={0,0,0,0};
            mma16816(d0, a0,a1,a2,a3, q0.x, q0.y);
            mma16816(d1, a0,a1,a2,a3, q1.x, q1.y);
            uint32_t w0 = ex2h2(d0[0], d0[1]);
            uint32_t w1 = ex2h2(d0[2], d0[3]);
            uint32_t w2 = ex2h2(d1[0], d1[1]);
            uint32_t w3 = ex2h2(d1[2], d1[3]);
            mma16816((st & 1) ? zB : zA, w0,w1,w2,w3, ONE2, ONE2);
        }
        __syncthreads();
    }
    if ((lane & 3) == 0) {
        int g = lane >> 2;
        g_Zpart[((size_t)z*BH + bh)*SS + trow + g]     = zA[0] + zB[0];
        g_Zpart[((size_t)z*BH + bh)*SS + trow + 8 + g] = zA[2] + zB[2];
    }
}

// ---------------- vnorm: vt[bh][e][t] = f16(v[bh][t][e] / Z_t), t-permuted ----------------
__global__ __launch_bounds__(256) void vnorm_kernel()
{
    int i = blockIdx.x * 256 + threadIdx.x;       // bh*SS + t
    float r = 1.0f / (g_Zpart[i] + g_Zpart[(size_t)BH*SS + i]);
    int bh = i >> 12, t = i & (SS-1);
    int tp = (t & ~15) + permpos(t & 15);
    const float4* vp = (const float4*)&g_v[(size_t)i*HDD];
    __half* dst = g_vt + (size_t)bh*HDD*SS + tp;
    #pragma unroll
    for (int j = 0; j < 4; j++) {
        float4 v = vp[j];
        dst[(size_t)(4*j+0)*SS] = __float2half(v.x * r);
        dst[(size_t)(4*j+1)*SS] = __float2half(v.y * r);
        dst[(size_t)(4*j+2)*SS] = __float2half(v.z * r);
        dst[(size_t)(4*j+3)*SS] = __float2half(v.w * r);
    }
}

// ---------------- Pass B: partial attended, k/vt tiles staged in smem ----------------
// grid (32, BH, 2), 256 thr. Warp owns s rows [x*128 + w*16, +16).
__global__ __launch_bounds__(256) void attendW_kernel()
{
    __shared__ __align__(16) __half sk[2][2048];   // 4 KB per buffer
    __shared__ __align__(16) __half sv[2][2048];
    int tid = threadIdx.x, w = tid >> 5, lane = tid & 31;
    int bh = blockIdx.y, z = blockIdx.z;
    int srow = blockIdx.x * 128 + w * 16;

    const __half* qb = g_q + (size_t)bh*SS*HDD;
    uint2 qa = *((const uint2*)(qb + (srow + (lane>>2))*HDD) + (lane&3));
    uint2 qc = *((const uint2*)(qb + (srow + 8 + (lane>>2))*HDD) + (lane&3));
    uint32_t a0 = qa.x, a2 = qa.y, a1 = qc.x, a3 = qc.y;

    const __half* kb = g_k + (size_t)bh*SS*HDD + (size_t)z*(SS/2)*HDD;
    const __half* vt = g_vt + (size_t)bh*HDD*SS + (size_t)z*(SS/2);

    // k loader: chunk tid -> row r = tid>>1, half-chunk c = tid&1
    int kr = tid >> 1, kc2 = tid & 1;
    uint32_t kdst = frag_dst(kr, kc2);
    const __half* ksrc = kb + kr*HDD + kc2*8;
    // vt loader: chunk tid -> e-row = tid>>4, t-chunk cv = tid&15
    // t-halves [8cv..8cv+7]: step = cv>>1, within-step c = cv&1, row index e (sel = e>>3, g = e&7)
    int ve = tid >> 4, vcv = tid & 15;
    uint32_t vdst = (uint32_t)((vcv>>1)*512 + (ve>>3)*256 + (ve&7)*32 + (vcv&1)*16);
    const __half* vsrc = vt + (size_t)ve*SS + vcv*8;

    uint32_t skb = smem_u32(sk), svb = smem_u32(sv);

    float oA[8] = {0,0,0,0,0,0,0,0};
    float oB[8] = {0,0,0,0,0,0,0,0};

    cpa16(skb + kdst, ksrc);
    cpa16(svb + vdst, vsrc);
    CP_COMMIT();

    const int NT = (SS/2)/128;   // 16 tiles
    for (int tile = 0; tile < NT; tile++) {
        int buf = tile & 1;
        if (tile + 1 < NT) {
            cpa16(skb + (buf^1)*4096 + kdst, ksrc + (size_t)(tile+1)*128*HDD);
            cpa16(svb + (buf^1)*4096 + vdst, vsrc + (size_t)(tile+1)*128);
            CP_COMMIT();
            CP_WAIT1();
        } else {
            CP_WAIT0();
        }
        __syncthreads();
        const char* kp = (const char*)sk + buf*4096 + lane*8;
        const char* vp = (const char*)sv + buf*4096 + lane*8;
        #pragma unroll
        for (int st = 0; st < 8; st++) {
            uint2 k0 = *(const uint2*)(kp + st*512);
            uint2 k1 = *(const uint2*)(kp + st*512 + 256);
            uint2 v0 = *(const uint2*)(vp + st*512);
            uint2 v1 = *(const uint2*)(vp + st*512 + 256);
            float d0[4] = {0,0,0,0}, d1[4] = {0,0,0,0};
            mma16816(d0, a0,a1,a2,a3, k0.x, k0.y);
            mma16816(d1, a0,a1,a2,a3, k1.x, k1.y);
            uint32_t w0 = ex2h2(d0[0], d0[1]);
            uint32_t w1 = ex2h2(d0[2], d0[3]);
            uint32_t w2 = ex2h2(d1[0], d1[1]);
            uint32_t w3 = ex2h2(d1[2], d1[3]);
            float* o = (st & 1) ? oB : oA;
            mma16816(o,     w0,w1,w2,w3, v0.x, v0.y);
            mma16816(o + 4, w0,w1,w2,w3, v1.x, v1.y);
        }
        __syncthreads();
    }

    int g = lane >> 2, tg = lane & 3;
    int b = bh >> 2, h = bh & 3;
    float* att = g_att + (size_t)z*BB*SS*DD;
    float* dst0 = att + (size_t)(b*SS + srow + g)*DD + h*HDD;
    float* dst1 = att + (size_t)(b*SS + srow + 8 + g)*DD + h*HDD;
    *(float2*)(dst0 + 2*tg)     = make_float2(oA[0]+oB[0], oA[1]+oB[1]);
    *(float2*)(dst1 + 2*tg)     = make_float2(oA[2]+oB[2], oA[3]+oB[3]);
    *(float2*)(dst0 + 8 + 2*tg) = make_float2(oA[4]+oB[4], oA[5]+oB[5]);
    *(float2*)(dst1 + 8 + 2*tg) = make_float2(oA[6]+oB[6], oA[7]+oB[7]);
}

// ---------------- out_proj: o = (att0+att1) @ Wo + bo, write exp(o), column partials ----------------
__global__ __launch_bounds__(256) void out_proj_kernel(
    const float* __restrict__ Wo, const float* __restrict__ bo)
{
    __shared__ float cs[16][64];
    __shared__ float wt[64][68];
    __shared__ float red[4][64];
    int tid = threadIdx.x;
    int row0 = blockIdx.x * 16;
    const float LOG2E = 1.4426950408889634f;

    for (int i = tid; i < 64*64; i += 256) {
        int c = i >> 6, d = i & 63;
        wt[d][c] = Wo[i];
    }
    for (int i = tid; i < 16*64; i += 256)
        cs[i>>6][i&63] = g_att[row0*64 + i] + g_att[(size_t)BB*SS*DD + row0*64 + i];
    __syncthreads();

    int d = tid & 63, r = tid >> 6;
    float bb = bo[d];
    const float4* wrow = (const float4*)&wt[d][0];
    float local = 0.f;

    #pragma unroll
    for (int rr = 0; rr < 4; rr++) {
        int row = r + rr*4;
        const float4* crow = (const float4*)&cs[row][0];
        float acc = 0.f;
        #pragma unroll
        for (int j = 0; j < 16; j++) {
            float4 cv = crow[j], wv = wrow[j];
            acc += cv.x*wv.x + cv.y*wv.y + cv.z*wv.z + cv.w*wv.w;
        }
        float ev = ex2f((acc + bb) * LOG2E);    // shift-free: |o| <= ~3
        g_o[(row0 + row)*64 + d] = ev;
        local += ev;
    }
    red[r][d] = local;
    __syncthreads();
    if (r == 0)
        g_Zop[blockIdx.x*64 + d] = red[0][d] + red[1][d] + red[2][d] + red[3][d];
}

// ---------------- zsum: per-(b,d) column sums from 256 block partials ----------------
__global__ __launch_bounds__(256) void zsum_kernel()
{
    __shared__ float red[4][64];
    int b = blockIdx.x;
    int d = threadIdx.x & 63, cg = threadIdx.x >> 6;
    float s = 0.f;
    for (int c = cg; c < 256; c += 4)
        s += g_Zop[(b*256 + c)*64 + d];
    red[cg][d] = s;
    __syncthreads();
    if (cg == 0)
        g_Zo[b*64 + d] = red[0][d] + red[1][d] + red[2][d] + red[3][d];
}

// ---------------- final: out = exp(o) / Z ----------------
__global__ __launch_bounds__(256) void final_scale_kernel(float* __restrict__ out)
{
    int idx = blockIdx.x * 256 + threadIdx.x;     // float4 index, 262144 total
    int row = idx >> 4;
    int b = row >> 12;
    int d4 = idx & 15;
    float4 e = ((const float4*)g_o)[idx];
    float4 zz = ((const float4*)g_Zo)[b*16 + d4];
    float4 o;
    o.x = __fdividef(e.x, zz.x);
    o.y = __fdividef(e.y, zz.y);
    o.z = __fdividef(e.z, zz.z);
    o.w = __fdividef(e.w, zz.w);
    ((float4*)out)[idx] = o;
}

// ---------------- launch ----------------
extern "C" void kernel_launch(void* const* d_in, const int* in_sizes, int n_in,
                              void* d_out, int out_size)
{
    const float* x  = (const float*)d_in[0];
    const float* Wq = (const float*)d_in[1];
    const float* bq = (const float*)d_in[2];
    const float* Wk = (const float*)d_in[3];
    const float* bk = (const float*)d_in[4];
    const float* Wv = (const float*)d_in[5];
    const float* bv = (const float*)d_in[6];
    const float* Wo = (const float*)d_in[7];
    const float* bo = (const float*)d_in[8];
    float* out = (float*)d_out;

    const float qscale = 0.25f * 1.4426950408889634f;  // 1/sqrt(HD) * log2(e)

    proj_kernel<<<dim3(BB*SS/16, 3), 256>>>(x, Wq, bq, Wk, bk, Wv, bv, qscale);

    colsumW_kernel<<<dim3(32, BH, 2), 256>>>();
    vnorm_kernel<<<(BH*SS)/256, 256>>>();
    attendW_kernel<<<dim3(32, BH, 2), 256>>>();

    out_proj_kernel<<<BB*SS/16, 256>>>(Wo, bo);
    zsum_kernel<<<BB, 256>>>();
    final_scale_kernel<<<(BB*SS*DD/4)/256, 256>>>(out);
}